// round 2
// baseline (speedup 1.0000x reference)
#include <cuda_runtime.h>
#include <cstddef>

#define DIM 128
#define MAX_N 100000   // max(N_USERS, N_ITEMS)

// Persistent scratch: two spmm ping-pong buffers + three layer outputs.
__device__ float g_T [(size_t)MAX_N * DIM];
__device__ float g_S [(size_t)MAX_N * DIM];
__device__ float g_H1[(size_t)MAX_N * DIM];
__device__ float g_H2[(size_t)MAX_N * DIM];
__device__ float g_H3[(size_t)MAX_N * DIM];

// Warp-per-edge COO SpMM: out[row] += val * h[col], D=128.
// Each lane handles 4 floats: one LDG.128 gather + one red.global.add.v4.f32.
__global__ void spmm_kernel(const int* __restrict__ rows,
                            const int* __restrict__ cols,
                            const float* __restrict__ vals,
                            const float* __restrict__ h,
                            float* __restrict__ out,
                            int nnz) {
    int gtid = blockIdx.x * blockDim.x + threadIdx.x;
    int e = gtid >> 5;
    if (e >= nnz) return;
    int lane = gtid & 31;

    int r = __ldg(rows + e);
    int c = __ldg(cols + e);
    float v = __ldg(vals + e);

    float4 x = __ldg(reinterpret_cast<const float4*>(h + (size_t)c * DIM) + lane);

    float* op = out + (size_t)r * DIM + (size_t)lane * 4;
    asm volatile("red.global.add.v4.f32 [%0], {%1, %2, %3, %4};"
                 :: "l"(op), "f"(x.x * v), "f"(x.y * v), "f"(x.z * v), "f"(x.w * v)
                 : "memory");
}

// out = 0.25 * (h0 + h1 + h2 + h3), float4-vectorized.
__global__ void mean4_kernel(float* __restrict__ out,
                             const float* __restrict__ h0,
                             const float* __restrict__ h1,
                             const float* __restrict__ h2,
                             const float* __restrict__ h3,
                             size_t n4) {
    size_t i = (size_t)blockIdx.x * blockDim.x + threadIdx.x;
    if (i >= n4) return;
    float4 a = reinterpret_cast<const float4*>(h0)[i];
    float4 b = reinterpret_cast<const float4*>(h1)[i];
    float4 c = reinterpret_cast<const float4*>(h2)[i];
    float4 d = reinterpret_cast<const float4*>(h3)[i];
    float4 o;
    o.x = 0.25f * (a.x + b.x + c.x + d.x);
    o.y = 0.25f * (a.y + b.y + c.y + d.y);
    o.z = 0.25f * (a.z + b.z + c.z + d.z);
    o.w = 0.25f * (a.w + b.w + c.w + d.w);
    reinterpret_cast<float4*>(out)[i] = o;
}

static inline void launch_spmm(const int* rows, const int* cols, const float* vals,
                               const float* h, float* out, int nnz) {
    int threads = 256;
    long long total = (long long)nnz * 32;
    int blocks = (int)((total + threads - 1) / threads);
    spmm_kernel<<<blocks, threads>>>(rows, cols, vals, h, out, nnz);
}

// One 3-layer branch. Layer: t = spmm(m2, h); s = spmm(m1, t); h' = spmm(mcat, s).
// Then out = mean(emb, h1, h2, h3).
static void run_branch(const float* emb, int n,
                       const int* r1, const int* c1, const float* v1, int nnz1,
                       const int* r2, const int* c2, const float* v2, int nnz2,
                       const int* rc, const int* cc, const float* vc, int nnzc,
                       float* out,
                       float* T, float* S, float* H1, float* H2, float* H3) {
    size_t nbytes = (size_t)n * DIM * sizeof(float);
    float* H[3] = {H1, H2, H3};

    const float* h = emb;
    for (int layer = 0; layer < 3; layer++) {
        cudaMemsetAsync(T, 0, nbytes);
        launch_spmm(r2, c2, v2, h, T, nnz2);

        cudaMemsetAsync(S, 0, nbytes);
        launch_spmm(r1, c1, v1, T, S, nnz1);

        cudaMemsetAsync(H[layer], 0, nbytes);
        launch_spmm(rc, cc, vc, S, H[layer], nnzc);

        h = H[layer];
    }

    size_t n4 = (size_t)n * DIM / 4;
    int threads = 256;
    int blocks = (int)((n4 + threads - 1) / threads);
    mean4_kernel<<<blocks, threads>>>(out, emb, H1, H2, H3, n4);
}

extern "C" void kernel_launch(void* const* d_in, const int* in_sizes, int n_in,
                              void* d_out, int out_size) {
    const float* user_emb = (const float*)d_in[0];
    const float* item_emb = (const float*)d_in[1];

    const int*   u1_rows = (const int*)  d_in[2];
    const int*   u1_cols = (const int*)  d_in[3];
    const float* u1_vals = (const float*)d_in[4];
    const int*   u2_rows = (const int*)  d_in[5];
    const int*   u2_cols = (const int*)  d_in[6];
    const float* u2_vals = (const float*)d_in[7];
    const int*   uc_rows = (const int*)  d_in[8];
    const int*   uc_cols = (const int*)  d_in[9];
    const float* uc_vals = (const float*)d_in[10];

    const int*   i1_rows = (const int*)  d_in[11];
    const int*   i1_cols = (const int*)  d_in[12];
    const float* i1_vals = (const float*)d_in[13];
    const int*   i2_rows = (const int*)  d_in[14];
    const int*   i2_cols = (const int*)  d_in[15];
    const float* i2_vals = (const float*)d_in[16];
    const int*   ic_rows = (const int*)  d_in[17];
    const int*   ic_cols = (const int*)  d_in[18];
    const float* ic_vals = (const float*)d_in[19];

    int n_users = in_sizes[0] / DIM;
    int n_items = in_sizes[1] / DIM;
    int nnz_u1 = in_sizes[2], nnz_u2 = in_sizes[5], nnz_uc = in_sizes[8];
    int nnz_i1 = in_sizes[11], nnz_i2 = in_sizes[14], nnz_ic = in_sizes[17];

    float *T, *S, *H1, *H2, *H3;
    cudaGetSymbolAddress((void**)&T,  g_T);
    cudaGetSymbolAddress((void**)&S,  g_S);
    cudaGetSymbolAddress((void**)&H1, g_H1);
    cudaGetSymbolAddress((void**)&H2, g_H2);
    cudaGetSymbolAddress((void**)&H3, g_H3);

    float* outU = (float*)d_out;
    float* outI = (float*)d_out + (size_t)n_users * DIM;

    run_branch(user_emb, n_users,
               u1_rows, u1_cols, u1_vals, nnz_u1,
               u2_rows, u2_cols, u2_vals, nnz_u2,
               uc_rows, uc_cols, uc_vals, nnz_uc,
               outU, T, S, H1, H2, H3);

    run_branch(item_emb, n_items,
               i1_rows, i1_cols, i1_vals, nnz_i1,
               i2_rows, i2_cols, i2_vals, nnz_i2,
               ic_rows, ic_cols, ic_vals, nnz_ic,
               outI, T, S, H1, H2, H3);
}

// round 3
// speedup vs baseline: 2.5583x; 2.5583x over previous
#include <cuda_runtime.h>
#include <cstddef>

#define DIM 128
#define MAX_N   100000
#define NNZ_U   3200000
#define NNZ_I   1600000
#define SCAN_T  1024

// ---- persistent scratch (static __device__: allocation-rule safe) ----
__device__ float g_T [(size_t)MAX_N * DIM];
__device__ float g_S [(size_t)MAX_N * DIM];
__device__ float g_H1[(size_t)MAX_N * DIM];
__device__ float g_H2[(size_t)MAX_N * DIM];
__device__ float g_H3[(size_t)MAX_N * DIM];

// CSR storage for the 6 matrices (0..2 user, 3..5 item)
__device__ int   g_offs[6][MAX_N + 2];
__device__ int   g_sc_u[3][NNZ_U];
__device__ float g_sv_u[3][NNZ_U];
__device__ int   g_sc_i[3][NNZ_I];
__device__ float g_sv_i[3][NNZ_I];

// build temps (reused sequentially per matrix)
__device__ int g_counts[MAX_N + 2];
__device__ int g_cur   [MAX_N + 2];
__device__ int g_bsums [SCAN_T];

// ---------------- CSR build ----------------
__global__ void hist_kernel(const int* __restrict__ rows, int* __restrict__ counts, int nnz) {
    int i = blockIdx.x * blockDim.x + threadIdx.x;
    if (i < nnz) atomicAdd(&counts[rows[i] + 1], 1);
}

// inclusive block scan (Hillis-Steele), emits per-block sums
__global__ void scan1_kernel(const int* __restrict__ in, int* __restrict__ out,
                             int* __restrict__ bsums, int m) {
    __shared__ int sh[SCAN_T];
    int i = blockIdx.x * SCAN_T + threadIdx.x;
    sh[threadIdx.x] = (i < m) ? in[i] : 0;
    __syncthreads();
    for (int off = 1; off < SCAN_T; off <<= 1) {
        int t = (threadIdx.x >= off) ? sh[threadIdx.x - off] : 0;
        __syncthreads();
        sh[threadIdx.x] += t;
        __syncthreads();
    }
    if (i < m) out[i] = sh[threadIdx.x];
    if (threadIdx.x == SCAN_T - 1) bsums[blockIdx.x] = sh[SCAN_T - 1];
}

// single-block exclusive scan of block sums (nb <= 1024)
__global__ void scan2_kernel(int* __restrict__ bsums, int nb) {
    __shared__ int sh[SCAN_T];
    sh[threadIdx.x] = (threadIdx.x < nb) ? bsums[threadIdx.x] : 0;
    __syncthreads();
    for (int off = 1; off < SCAN_T; off <<= 1) {
        int t = (threadIdx.x >= off) ? sh[threadIdx.x - off] : 0;
        __syncthreads();
        sh[threadIdx.x] += t;
        __syncthreads();
    }
    int ex = (threadIdx.x == 0) ? 0 : sh[threadIdx.x - 1];
    if (threadIdx.x < nb) bsums[threadIdx.x] = ex;
}

__global__ void scan3_kernel(int* __restrict__ out, const int* __restrict__ bsums, int m) {
    int i = blockIdx.x * SCAN_T + threadIdx.x;
    if (i < m) out[i] += bsums[blockIdx.x];
}

__global__ void scatter_kernel(const int* __restrict__ rows, const int* __restrict__ cols,
                               const float* __restrict__ vals, int* __restrict__ cur,
                               int* __restrict__ sc, float* __restrict__ sv, int nnz) {
    int i = blockIdx.x * blockDim.x + threadIdx.x;
    if (i >= nnz) return;
    int r = rows[i];
    int p = atomicAdd(&cur[r], 1);
    sc[p] = cols[i];
    sv[p] = vals[i];
}

// ---------------- CSR SpMM: row per warp, register accumulator ----------------
__global__ void spmm_csr_kernel(const int* __restrict__ offs,
                                const int* __restrict__ sc,
                                const float* __restrict__ sv,
                                const float* __restrict__ h,
                                float* __restrict__ out, int n) {
    int w = (blockIdx.x * blockDim.x + threadIdx.x) >> 5;
    if (w >= n) return;
    int lane = threadIdx.x & 31;

    int beg = __ldg(offs + w);
    int end = __ldg(offs + w + 1);

    float4 acc = make_float4(0.f, 0.f, 0.f, 0.f);
    for (int base = beg; base < end; base += 32) {
        int e = base + lane;
        int c = 0; float v = 0.f;
        if (e < end) { c = __ldg(sc + e); v = __ldg(sv + e); }
        int cnt = min(32, end - base);
        #pragma unroll 4
        for (int j = 0; j < cnt; j++) {
            int   cj = __shfl_sync(0xffffffffu, c, j);
            float vj = __shfl_sync(0xffffffffu, v, j);
            float4 x = __ldg(reinterpret_cast<const float4*>(h + (size_t)cj * DIM) + lane);
            acc.x += vj * x.x;
            acc.y += vj * x.y;
            acc.z += vj * x.z;
            acc.w += vj * x.w;
        }
    }
    reinterpret_cast<float4*>(out)[(size_t)w * (DIM / 4) + lane] = acc;
}

// out = 0.25 * (h0 + h1 + h2 + h3)
__global__ void mean4_kernel(float* __restrict__ out,
                             const float* __restrict__ h0, const float* __restrict__ h1,
                             const float* __restrict__ h2, const float* __restrict__ h3,
                             size_t n4) {
    size_t i = (size_t)blockIdx.x * blockDim.x + threadIdx.x;
    if (i >= n4) return;
    float4 a = reinterpret_cast<const float4*>(h0)[i];
    float4 b = reinterpret_cast<const float4*>(h1)[i];
    float4 c = reinterpret_cast<const float4*>(h2)[i];
    float4 d = reinterpret_cast<const float4*>(h3)[i];
    float4 o;
    o.x = 0.25f * (a.x + b.x + c.x + d.x);
    o.y = 0.25f * (a.y + b.y + c.y + d.y);
    o.z = 0.25f * (a.z + b.z + c.z + d.z);
    o.w = 0.25f * (a.w + b.w + c.w + d.w);
    reinterpret_cast<float4*>(out)[i] = o;
}

// ---------------- host-side helpers ----------------
static void build_csr(const int* rows, const int* cols, const float* vals,
                      int nnz, int n,
                      int* offs, int* sc, float* sv,
                      int* counts, int* cur, int* bsums) {
    int m = n + 1;
    cudaMemsetAsync(counts, 0, m * sizeof(int));
    hist_kernel<<<(nnz + 255) / 256, 256>>>(rows, counts, nnz);
    int nb = (m + SCAN_T - 1) / SCAN_T;
    scan1_kernel<<<nb, SCAN_T>>>(counts, offs, bsums, m);
    scan2_kernel<<<1, SCAN_T>>>(bsums, nb);
    scan3_kernel<<<nb, SCAN_T>>>(offs, bsums, m);
    cudaMemcpyAsync(cur, offs, n * sizeof(int), cudaMemcpyDeviceToDevice);
    scatter_kernel<<<(nnz + 255) / 256, 256>>>(rows, cols, vals, cur, sc, sv, nnz);
}

static inline void launch_spmm(const int* offs, const int* sc, const float* sv,
                               const float* h, float* out, int n) {
    long long total = (long long)n * 32;
    int blocks = (int)((total + 255) / 256);
    spmm_csr_kernel<<<blocks, 256>>>(offs, sc, sv, h, out, n);
}

static void run_branch(const float* emb, int n,
                       const int* offs1, const int* sc1, const float* sv1,
                       const int* offs2, const int* sc2, const float* sv2,
                       const int* offsc, const int* scc, const float* svc,
                       float* out,
                       float* T, float* S, float* H1, float* H2, float* H3) {
    float* H[3] = {H1, H2, H3};
    const float* h = emb;
    for (int layer = 0; layer < 3; layer++) {
        launch_spmm(offs2, sc2, sv2, h, T, n);
        launch_spmm(offs1, sc1, sv1, T, S, n);
        launch_spmm(offsc, scc, svc, S, H[layer], n);
        h = H[layer];
    }
    size_t n4 = (size_t)n * DIM / 4;
    mean4_kernel<<<(int)((n4 + 255) / 256), 256>>>(out, emb, H1, H2, H3, n4);
}

extern "C" void kernel_launch(void* const* d_in, const int* in_sizes, int n_in,
                              void* d_out, int out_size) {
    const float* user_emb = (const float*)d_in[0];
    const float* item_emb = (const float*)d_in[1];

    // matrix inputs: (rows, cols, vals) × {u1,u2,ucat,i1,i2,icat}
    const int*   mr[6]; const int* mc[6]; const float* mv[6]; int mn[6]; int mrows[6];
    for (int k = 0; k < 6; k++) {
        mr[k] = (const int*)  d_in[2 + 3 * k];
        mc[k] = (const int*)  d_in[3 + 3 * k];
        mv[k] = (const float*)d_in[4 + 3 * k];
        mn[k] = in_sizes[2 + 3 * k];
    }
    int n_users = in_sizes[0] / DIM;
    int n_items = in_sizes[1] / DIM;
    mrows[0] = mrows[1] = mrows[2] = n_users;   // u1, u2, ucat
    mrows[3] = mrows[4] = mrows[5] = n_items;   // i1, i2, icat

    float *T, *S, *H1, *H2, *H3;
    cudaGetSymbolAddress((void**)&T,  g_T);
    cudaGetSymbolAddress((void**)&S,  g_S);
    cudaGetSymbolAddress((void**)&H1, g_H1);
    cudaGetSymbolAddress((void**)&H2, g_H2);
    cudaGetSymbolAddress((void**)&H3, g_H3);

    int *counts, *cur, *bsums;
    cudaGetSymbolAddress((void**)&counts, g_counts);
    cudaGetSymbolAddress((void**)&cur,    g_cur);
    cudaGetSymbolAddress((void**)&bsums,  g_bsums);

    int* offs[6]; int* sc[6]; float* sv[6];
    {
        int*   offs_base; cudaGetSymbolAddress((void**)&offs_base, g_offs);
        int*   scu; cudaGetSymbolAddress((void**)&scu, g_sc_u);
        float* svu; cudaGetSymbolAddress((void**)&svu, g_sv_u);
        int*   sci; cudaGetSymbolAddress((void**)&sci, g_sc_i);
        float* svi; cudaGetSymbolAddress((void**)&svi, g_sv_i);
        for (int k = 0; k < 6; k++) offs[k] = offs_base + (size_t)k * (MAX_N + 2);
        for (int k = 0; k < 3; k++) { sc[k]     = scu + (size_t)k * NNZ_U; sv[k]     = svu + (size_t)k * NNZ_U; }
        for (int k = 0; k < 3; k++) { sc[3 + k] = sci + (size_t)k * NNZ_I; sv[3 + k] = svi + (size_t)k * NNZ_I; }
    }

    for (int k = 0; k < 6; k++)
        build_csr(mr[k], mc[k], mv[k], mn[k], mrows[k],
                  offs[k], sc[k], sv[k], counts, cur, bsums);

    float* outU = (float*)d_out;
    float* outI = (float*)d_out + (size_t)n_users * DIM;

    // order within branch: m2 then m1 then mcat  (indices: u1=0,u2=1,ucat=2)
    run_branch(user_emb, n_users,
               offs[0], sc[0], sv[0],
               offs[1], sc[1], sv[1],
               offs[2], sc[2], sv[2],
               outU, T, S, H1, H2, H3);

    run_branch(item_emb, n_items,
               offs[3], sc[3], sv[3],
               offs[4], sc[4], sv[4],
               offs[5], sc[5], sv[5],
               outI, T, S, H1, H2, H3);
}

// round 4
// speedup vs baseline: 3.4349x; 1.3427x over previous
#include <cuda_runtime.h>
#include <cuda_fp16.h>
#include <cstddef>

#define DIM 128
#define MAX_N   100000
#define NNZ_U   3200000
#define NNZ_I   1600000
#define SCAN_T  1024

// Per-stage fp16 storage scale (1/4) and its exact compensations in the mean.
#define STAGE_SCALE 0.25f

// ---- persistent scratch ----
// fp16 intermediates (gathered stages)
__device__ __half g_T [(size_t)MAX_N * DIM];
__device__ __half g_S [(size_t)MAX_N * DIM];
__device__ __half g_H1[(size_t)MAX_N * DIM];
__device__ __half g_H2[(size_t)MAX_N * DIM];
// final layer output per branch: fp32, never gathered
__device__ float  g_H3[(size_t)MAX_N * DIM];

// CSR storage: packed (col, val_bits) edges
__device__ int  g_offs[6][MAX_N + 2];
__device__ int2 g_e_u[3][NNZ_U];
__device__ int2 g_e_i[3][NNZ_I];

// build temps
__device__ int g_counts[MAX_N + 2];
__device__ int g_cur   [MAX_N + 2];
__device__ int g_bsums [SCAN_T];

// ---------------- CSR build ----------------
__global__ void hist_kernel(const int* __restrict__ rows, int* __restrict__ counts, int nnz) {
    int i = blockIdx.x * blockDim.x + threadIdx.x;
    if (i < nnz) atomicAdd(&counts[rows[i] + 1], 1);
}

__global__ void scan1_kernel(const int* __restrict__ in, int* __restrict__ out,
                             int* __restrict__ bsums, int m) {
    __shared__ int sh[SCAN_T];
    int i = blockIdx.x * SCAN_T + threadIdx.x;
    sh[threadIdx.x] = (i < m) ? in[i] : 0;
    __syncthreads();
    for (int off = 1; off < SCAN_T; off <<= 1) {
        int t = (threadIdx.x >= off) ? sh[threadIdx.x - off] : 0;
        __syncthreads();
        sh[threadIdx.x] += t;
        __syncthreads();
    }
    if (i < m) out[i] = sh[threadIdx.x];
    if (threadIdx.x == SCAN_T - 1) bsums[blockIdx.x] = sh[SCAN_T - 1];
}

__global__ void scan2_kernel(int* __restrict__ bsums, int nb) {
    __shared__ int sh[SCAN_T];
    sh[threadIdx.x] = (threadIdx.x < nb) ? bsums[threadIdx.x] : 0;
    __syncthreads();
    for (int off = 1; off < SCAN_T; off <<= 1) {
        int t = (threadIdx.x >= off) ? sh[threadIdx.x - off] : 0;
        __syncthreads();
        sh[threadIdx.x] += t;
        __syncthreads();
    }
    int ex = (threadIdx.x == 0) ? 0 : sh[threadIdx.x - 1];
    if (threadIdx.x < nb) bsums[threadIdx.x] = ex;
}

__global__ void scan3_kernel(int* __restrict__ out, const int* __restrict__ bsums, int m) {
    int i = blockIdx.x * SCAN_T + threadIdx.x;
    if (i < m) out[i] += bsums[blockIdx.x];
}

__global__ void scatter_kernel(const int* __restrict__ rows, const int* __restrict__ cols,
                               const float* __restrict__ vals, int* __restrict__ cur,
                               int2* __restrict__ edges, int nnz) {
    int i = blockIdx.x * blockDim.x + threadIdx.x;
    if (i >= nnz) return;
    int r = rows[i];
    int p = atomicAdd(&cur[r], 1);
    edges[p] = make_int2(cols[i], __float_as_int(vals[i]));
}

// ---------------- CSR SpMM: row per warp, register accumulator ----------------
// IN_HALF: gather source is fp16 (8B/lane) vs fp32 (16B/lane)
// OUT_HALF: store result as fp16 scaled by STAGE_SCALE, else fp32 unscaled
template <bool IN_HALF, bool OUT_HALF>
__global__ void spmm_csr_kernel(const int* __restrict__ offs,
                                const int2* __restrict__ edges,
                                const void* __restrict__ h,
                                void* __restrict__ out, int n) {
    int w = (blockIdx.x * blockDim.x + threadIdx.x) >> 5;
    if (w >= n) return;
    int lane = threadIdx.x & 31;

    int beg = __ldg(offs + w);
    int end = __ldg(offs + w + 1);

    float4 acc = make_float4(0.f, 0.f, 0.f, 0.f);
    for (int base = beg; base < end; base += 32) {
        int e = base + lane;
        int c = 0; float v = 0.f;
        if (e < end) {
            int2 ed = __ldg(edges + e);
            c = ed.x;
            v = __int_as_float(ed.y);
        }
        int cnt = min(32, end - base);
        #pragma unroll 4
        for (int j = 0; j < cnt; j++) {
            int   cj = __shfl_sync(0xffffffffu, c, j);
            float vj = __shfl_sync(0xffffffffu, v, j);
            float4 x;
            if (IN_HALF) {
                uint2 u = __ldg(reinterpret_cast<const uint2*>(h) + (size_t)cj * (DIM / 4) + lane);
                float2 lo = __half22float2(*reinterpret_cast<__half2*>(&u.x));
                float2 hi = __half22float2(*reinterpret_cast<__half2*>(&u.y));
                x = make_float4(lo.x, lo.y, hi.x, hi.y);
            } else {
                x = __ldg(reinterpret_cast<const float4*>(h) + (size_t)cj * (DIM / 4) + lane);
            }
            acc.x += vj * x.x;
            acc.y += vj * x.y;
            acc.z += vj * x.z;
            acc.w += vj * x.w;
        }
    }

    if (OUT_HALF) {
        uint2 o;
        __half2 p0 = __floats2half2_rn(acc.x * STAGE_SCALE, acc.y * STAGE_SCALE);
        __half2 p1 = __floats2half2_rn(acc.z * STAGE_SCALE, acc.w * STAGE_SCALE);
        o.x = *reinterpret_cast<unsigned*>(&p0);
        o.y = *reinterpret_cast<unsigned*>(&p1);
        reinterpret_cast<uint2*>(out)[(size_t)w * (DIM / 4) + lane] = o;
    } else {
        reinterpret_cast<float4*>(out)[(size_t)w * (DIM / 4) + lane] = acc;
    }
}

// out = 0.25 * (h0 + 64*H1 + 4096*H2 + 65536*H3)   (exact scale compensation)
__global__ void mean4_kernel(float* __restrict__ out,
                             const float* __restrict__ h0,
                             const __half* __restrict__ h1,
                             const __half* __restrict__ h2,
                             const float* __restrict__ h3,
                             size_t n4) {
    size_t i = (size_t)blockIdx.x * blockDim.x + threadIdx.x;
    if (i >= n4) return;
    float4 a = reinterpret_cast<const float4*>(h0)[i];
    uint2 ub = reinterpret_cast<const uint2*>(h1)[i];
    uint2 uc = reinterpret_cast<const uint2*>(h2)[i];
    float4 d = reinterpret_cast<const float4*>(h3)[i];

    float2 b0 = __half22float2(*reinterpret_cast<__half2*>(&ub.x));
    float2 b1 = __half22float2(*reinterpret_cast<__half2*>(&ub.y));
    float2 c0 = __half22float2(*reinterpret_cast<__half2*>(&uc.x));
    float2 c1 = __half22float2(*reinterpret_cast<__half2*>(&uc.y));

    const float w1 = 64.0f, w2 = 4096.0f, w3 = 65536.0f;
    float4 o;
    o.x = 0.25f * (a.x + w1 * b0.x + w2 * c0.x + w3 * d.x);
    o.y = 0.25f * (a.y + w1 * b0.y + w2 * c0.y + w3 * d.y);
    o.z = 0.25f * (a.z + w1 * b1.x + w2 * c1.x + w3 * d.z);
    o.w = 0.25f * (a.w + w1 * b1.y + w2 * c1.y + w3 * d.w);
    reinterpret_cast<float4*>(out)[i] = o;
}

// ---------------- host-side helpers ----------------
static void build_csr(const int* rows, const int* cols, const float* vals,
                      int nnz, int n,
                      int* offs, int2* edges,
                      int* counts, int* cur, int* bsums) {
    int m = n + 1;
    cudaMemsetAsync(counts, 0, m * sizeof(int));
    hist_kernel<<<(nnz + 255) / 256, 256>>>(rows, counts, nnz);
    int nb = (m + SCAN_T - 1) / SCAN_T;
    scan1_kernel<<<nb, SCAN_T>>>(counts, offs, bsums, m);
    scan2_kernel<<<1, SCAN_T>>>(bsums, nb);
    scan3_kernel<<<nb, SCAN_T>>>(offs, bsums, m);
    cudaMemcpyAsync(cur, offs, n * sizeof(int), cudaMemcpyDeviceToDevice);
    scatter_kernel<<<(nnz + 255) / 256, 256>>>(rows, cols, vals, cur, edges, nnz);
}

template <bool IN_HALF, bool OUT_HALF>
static inline void launch_spmm(const int* offs, const int2* edges,
                               const void* h, void* out, int n) {
    long long total = (long long)n * 32;
    int blocks = (int)((total + 255) / 256);
    spmm_csr_kernel<IN_HALF, OUT_HALF><<<blocks, 256>>>(offs, edges, h, out, n);
}

// Branch chain (per layer: m2, then m1, then mcat):
//   T = spmm(m2, h)   S = spmm(m1, T)   H = spmm(mcat, S)
// All intermediates fp16 scaled by 1/4 per store, except H3 (fp32, unscaled).
static void run_branch(const float* emb, int n,
                       const int* offs1, const int2* e1,
                       const int* offs2, const int2* e2,
                       const int* offsc, const int2* ec,
                       float* out,
                       __half* T, __half* S, __half* H1, __half* H2, float* H3) {
    // layer 1 (input fp32)
    launch_spmm<false, true>(offs2, e2, emb, T, n);
    launch_spmm<true,  true>(offs1, e1, T,   S, n);
    launch_spmm<true,  true>(offsc, ec, S,  H1, n);
    // layer 2
    launch_spmm<true,  true>(offs2, e2, H1, T, n);
    launch_spmm<true,  true>(offs1, e1, T,  S, n);
    launch_spmm<true,  true>(offsc, ec, S, H2, n);
    // layer 3 (final output fp32)
    launch_spmm<true,  true>(offs2, e2, H2, T, n);
    launch_spmm<true,  true>(offs1, e1, T,  S, n);
    launch_spmm<true, false>(offsc, ec, S, H3, n);

    size_t n4 = (size_t)n * DIM / 4;
    mean4_kernel<<<(int)((n4 + 255) / 256), 256>>>(out, emb, H1, H2, H3, n4);
}

extern "C" void kernel_launch(void* const* d_in, const int* in_sizes, int n_in,
                              void* d_out, int out_size) {
    const float* user_emb = (const float*)d_in[0];
    const float* item_emb = (const float*)d_in[1];

    const int* mr[6]; const int* mc[6]; const float* mv[6]; int mn[6]; int mrows[6];
    for (int k = 0; k < 6; k++) {
        mr[k] = (const int*)  d_in[2 + 3 * k];
        mc[k] = (const int*)  d_in[3 + 3 * k];
        mv[k] = (const float*)d_in[4 + 3 * k];
        mn[k] = in_sizes[2 + 3 * k];
    }
    int n_users = in_sizes[0] / DIM;
    int n_items = in_sizes[1] / DIM;
    mrows[0] = mrows[1] = mrows[2] = n_users;   // u1, u2, ucat
    mrows[3] = mrows[4] = mrows[5] = n_items;   // i1, i2, icat

    __half *T, *S, *H1, *H2; float* H3;
    cudaGetSymbolAddress((void**)&T,  g_T);
    cudaGetSymbolAddress((void**)&S,  g_S);
    cudaGetSymbolAddress((void**)&H1, g_H1);
    cudaGetSymbolAddress((void**)&H2, g_H2);
    cudaGetSymbolAddress((void**)&H3, g_H3);

    int *counts, *cur, *bsums;
    cudaGetSymbolAddress((void**)&counts, g_counts);
    cudaGetSymbolAddress((void**)&cur,    g_cur);
    cudaGetSymbolAddress((void**)&bsums,  g_bsums);

    int* offs[6]; int2* ed[6];
    {
        int*  offs_base; cudaGetSymbolAddress((void**)&offs_base, g_offs);
        int2* eu; cudaGetSymbolAddress((void**)&eu, g_e_u);
        int2* ei; cudaGetSymbolAddress((void**)&ei, g_e_i);
        for (int k = 0; k < 6; k++) offs[k] = offs_base + (size_t)k * (MAX_N + 2);
        for (int k = 0; k < 3; k++) ed[k]     = eu + (size_t)k * NNZ_U;
        for (int k = 0; k < 3; k++) ed[3 + k] = ei + (size_t)k * NNZ_I;
    }

    for (int k = 0; k < 6; k++)
        build_csr(mr[k], mc[k], mv[k], mn[k], mrows[k],
                  offs[k], ed[k], counts, cur, bsums);

    float* outU = (float*)d_out;
    float* outI = (float*)d_out + (size_t)n_users * DIM;

    run_branch(user_emb, n_users,
               offs[0], ed[0], offs[1], ed[1], offs[2], ed[2],
               outU, T, S, H1, H2, H3);

    run_branch(item_emb, n_items,
               offs[3], ed[3], offs[4], ed[4], offs[5], ed[5],
               outI, T, S, H1, H2, H3);
}

// round 5
// speedup vs baseline: 3.5904x; 1.0453x over previous
#include <cuda_runtime.h>
#include <cuda_fp16.h>
#include <cstddef>

#define DIM 128
#define MAX_USERS 100000
#define MAX_ITEMS 50000
#define MAX_NT   (MAX_USERS + MAX_ITEMS)
#define NNZ_U   3200000
#define NNZ_I   1600000
#define NNZ_TOT (3 * NNZ_U + 3 * NNZ_I)
#define CNT_L   (3 * (MAX_USERS + 1) + 3 * (MAX_ITEMS + 1))
#define SCAN_T  1024

#define STAGE_SCALE 0.25f

// ---- persistent scratch ----
__device__ __half g_E [(size_t)MAX_NT * DIM];   // fp16 embeddings (both branches)
__device__ __half g_T [(size_t)MAX_NT * DIM];
__device__ __half g_S [(size_t)MAX_NT * DIM];
__device__ __half g_H1[(size_t)MAX_NT * DIM];
__device__ __half g_H2[(size_t)MAX_NT * DIM];
__device__ float  g_H3[(size_t)MAX_NT * DIM];

__device__ int2 g_edges[NNZ_TOT];               // packed (col, val_bits), global slab
__device__ int  g_counts[CNT_L];
__device__ int  g_offs  [CNT_L];
__device__ int  g_cur   [CNT_L];
__device__ int  g_bsums [SCAN_T];

struct BuildArgs {
    const int*   rows[6];
    const int*   cols[6];
    const float* vals[6];
    int ebase[7];   // cumulative edge bases (global edge slab)
    int cbase[7];   // cumulative count-array bases
};

// ---------------- unified CSR build ----------------
__global__ void hist_all_kernel(BuildArgs a, int* __restrict__ counts, int total) {
    int i = blockIdx.x * blockDim.x + threadIdx.x;
    if (i >= total) return;
    int k = 0;
    #pragma unroll
    for (int j = 1; j < 6; j++) if (i >= a.ebase[j]) k = j;
    int local = i - a.ebase[k];
    int r = __ldg(a.rows[k] + local);
    atomicAdd(&counts[a.cbase[k] + r + 1], 1);
}

__global__ void scan1_kernel(const int* __restrict__ in, int* __restrict__ out,
                             int* __restrict__ bsums, int m) {
    __shared__ int sh[SCAN_T];
    int i = blockIdx.x * SCAN_T + threadIdx.x;
    sh[threadIdx.x] = (i < m) ? in[i] : 0;
    __syncthreads();
    for (int off = 1; off < SCAN_T; off <<= 1) {
        int t = (threadIdx.x >= off) ? sh[threadIdx.x - off] : 0;
        __syncthreads();
        sh[threadIdx.x] += t;
        __syncthreads();
    }
    if (i < m) out[i] = sh[threadIdx.x];
    if (threadIdx.x == SCAN_T - 1) bsums[blockIdx.x] = sh[SCAN_T - 1];
}

__global__ void scan2_kernel(int* __restrict__ bsums, int nb) {
    __shared__ int sh[SCAN_T];
    sh[threadIdx.x] = (threadIdx.x < nb) ? bsums[threadIdx.x] : 0;
    __syncthreads();
    for (int off = 1; off < SCAN_T; off <<= 1) {
        int t = (threadIdx.x >= off) ? sh[threadIdx.x - off] : 0;
        __syncthreads();
        sh[threadIdx.x] += t;
        __syncthreads();
    }
    int ex = (threadIdx.x == 0) ? 0 : sh[threadIdx.x - 1];
    if (threadIdx.x < nb) bsums[threadIdx.x] = ex;
}

__global__ void scan3_kernel(int* __restrict__ out, const int* __restrict__ bsums, int m) {
    int i = blockIdx.x * SCAN_T + threadIdx.x;
    if (i < m) out[i] += bsums[blockIdx.x];
}

__global__ void scatter_all_kernel(BuildArgs a, int* __restrict__ cur,
                                   int2* __restrict__ edges, int total) {
    int i = blockIdx.x * blockDim.x + threadIdx.x;
    if (i >= total) return;
    int k = 0;
    #pragma unroll
    for (int j = 1; j < 6; j++) if (i >= a.ebase[j]) k = j;
    int local = i - a.ebase[k];
    int r = __ldg(a.rows[k] + local);
    int p = atomicAdd(&cur[a.cbase[k] + r], 1);
    edges[p] = make_int2(__ldg(a.cols[k] + local),
                         __float_as_int(__ldg(a.vals[k] + local)));
}

// ---------------- embedding convert (fp32 -> fp16, combined layout) ----------------
__global__ void convert_emb_kernel(const float* __restrict__ ue,
                                   const float* __restrict__ ie,
                                   __half* __restrict__ E,
                                   size_t u4, size_t n4) {
    size_t i = (size_t)blockIdx.x * blockDim.x + threadIdx.x;
    if (i >= n4) return;
    float4 x = (i < u4) ? __ldg(reinterpret_cast<const float4*>(ue) + i)
                        : __ldg(reinterpret_cast<const float4*>(ie) + (i - u4));
    __half2 p0 = __floats2half2_rn(x.x, x.y);
    __half2 p1 = __floats2half2_rn(x.z, x.w);
    uint2 o;
    o.x = *reinterpret_cast<unsigned*>(&p0);
    o.y = *reinterpret_cast<unsigned*>(&p1);
    reinterpret_cast<uint2*>(E)[i] = o;
}

// ---------------- fused CSR SpMM: both branches, row per warp ----------------
template <bool OUT_HALF>
__global__ void spmm_fused_kernel(const int* __restrict__ offs_u,
                                  const int* __restrict__ offs_i,
                                  const int2* __restrict__ edges,
                                  const __half* __restrict__ h,
                                  void* __restrict__ out,
                                  int n_users, int n_total) {
    int w = (blockIdx.x * blockDim.x + threadIdx.x) >> 5;
    if (w >= n_total) return;
    int lane = threadIdx.x & 31;

    int beg, end;
    size_t colbase;
    if (w < n_users) {
        beg = __ldg(offs_u + w);
        end = __ldg(offs_u + w + 1);
        colbase = 0;
    } else {
        int r = w - n_users;
        beg = __ldg(offs_i + r);
        end = __ldg(offs_i + r + 1);
        colbase = (size_t)n_users;
    }

    const uint2* hrow = reinterpret_cast<const uint2*>(h);
    float4 acc = make_float4(0.f, 0.f, 0.f, 0.f);

    for (int base = beg; base < end; base += 32) {
        int e = base + lane;
        int c = 0; float v = 0.f;
        if (e < end) {
            int2 ed = __ldg(edges + e);
            c = ed.x;
            v = __int_as_float(ed.y);
        }
        int cnt = min(32, end - base);
        #pragma unroll 4
        for (int j = 0; j < cnt; j++) {
            int   cj = __shfl_sync(0xffffffffu, c, j);
            float vj = __shfl_sync(0xffffffffu, v, j);
            uint2 u = __ldg(hrow + (colbase + cj) * (DIM / 4) + lane);
            float2 lo = __half22float2(*reinterpret_cast<__half2*>(&u.x));
            float2 hi = __half22float2(*reinterpret_cast<__half2*>(&u.y));
            acc.x += vj * lo.x;
            acc.y += vj * lo.y;
            acc.z += vj * hi.x;
            acc.w += vj * hi.y;
        }
    }

    if (OUT_HALF) {
        __half2 p0 = __floats2half2_rn(acc.x * STAGE_SCALE, acc.y * STAGE_SCALE);
        __half2 p1 = __floats2half2_rn(acc.z * STAGE_SCALE, acc.w * STAGE_SCALE);
        uint2 o;
        o.x = *reinterpret_cast<unsigned*>(&p0);
        o.y = *reinterpret_cast<unsigned*>(&p1);
        reinterpret_cast<uint2*>(out)[(size_t)w * (DIM / 4) + lane] = o;
    } else {
        reinterpret_cast<float4*>(out)[(size_t)w * (DIM / 4) + lane] = acc;
    }
}

// out = 0.25 * (h0 + 64*H1 + 4096*H2 + 65536*H3), combined layout
__global__ void mean4_kernel(float* __restrict__ out,
                             const float* __restrict__ ue,
                             const float* __restrict__ ie,
                             const __half* __restrict__ h1,
                             const __half* __restrict__ h2,
                             const float* __restrict__ h3,
                             size_t u4, size_t n4) {
    size_t i = (size_t)blockIdx.x * blockDim.x + threadIdx.x;
    if (i >= n4) return;
    float4 a = (i < u4) ? reinterpret_cast<const float4*>(ue)[i]
                        : reinterpret_cast<const float4*>(ie)[i - u4];
    uint2 ub = reinterpret_cast<const uint2*>(h1)[i];
    uint2 uc = reinterpret_cast<const uint2*>(h2)[i];
    float4 d = reinterpret_cast<const float4*>(h3)[i];

    float2 b0 = __half22float2(*reinterpret_cast<__half2*>(&ub.x));
    float2 b1 = __half22float2(*reinterpret_cast<__half2*>(&ub.y));
    float2 c0 = __half22float2(*reinterpret_cast<__half2*>(&uc.x));
    float2 c1 = __half22float2(*reinterpret_cast<__half2*>(&uc.y));

    const float w1 = 64.0f, w2 = 4096.0f, w3 = 65536.0f;
    float4 o;
    o.x = 0.25f * (a.x + w1 * b0.x + w2 * c0.x + w3 * d.x);
    o.y = 0.25f * (a.y + w1 * b0.y + w2 * c0.y + w3 * d.y);
    o.z = 0.25f * (a.z + w1 * b1.x + w2 * c1.x + w3 * d.z);
    o.w = 0.25f * (a.w + w1 * b1.y + w2 * c1.y + w3 * d.w);
    reinterpret_cast<float4*>(out)[i] = o;
}

template <bool OUT_HALF>
static inline void launch_spmm(const int* offs_u, const int* offs_i, const int2* edges,
                               const __half* h, void* out, int n_users, int n_total) {
    long long total = (long long)n_total * 32;
    int blocks = (int)((total + 255) / 256);
    spmm_fused_kernel<OUT_HALF><<<blocks, 256>>>(offs_u, offs_i, edges, h, out, n_users, n_total);
}

extern "C" void kernel_launch(void* const* d_in, const int* in_sizes, int n_in,
                              void* d_out, int out_size) {
    const float* user_emb = (const float*)d_in[0];
    const float* item_emb = (const float*)d_in[1];

    BuildArgs a;
    int mrows[6];
    int n_users = in_sizes[0] / DIM;
    int n_items = in_sizes[1] / DIM;
    mrows[0] = mrows[1] = mrows[2] = n_users;   // u1, u2, ucat
    mrows[3] = mrows[4] = mrows[5] = n_items;   // i1, i2, icat

    a.ebase[0] = 0;
    a.cbase[0] = 0;
    for (int k = 0; k < 6; k++) {
        a.rows[k] = (const int*)  d_in[2 + 3 * k];
        a.cols[k] = (const int*)  d_in[3 + 3 * k];
        a.vals[k] = (const float*)d_in[4 + 3 * k];
        a.ebase[k + 1] = a.ebase[k] + in_sizes[2 + 3 * k];
        a.cbase[k + 1] = a.cbase[k] + mrows[k] + 1;
    }
    int total_nnz = a.ebase[6];
    int L = a.cbase[6];
    int n_total = n_users + n_items;

    __half *E, *T, *S, *H1, *H2; float* H3;
    cudaGetSymbolAddress((void**)&E,  g_E);
    cudaGetSymbolAddress((void**)&T,  g_T);
    cudaGetSymbolAddress((void**)&S,  g_S);
    cudaGetSymbolAddress((void**)&H1, g_H1);
    cudaGetSymbolAddress((void**)&H2, g_H2);
    cudaGetSymbolAddress((void**)&H3, g_H3);

    int *counts, *offs, *cur, *bsums; int2* edges;
    cudaGetSymbolAddress((void**)&counts, g_counts);
    cudaGetSymbolAddress((void**)&offs,   g_offs);
    cudaGetSymbolAddress((void**)&cur,    g_cur);
    cudaGetSymbolAddress((void**)&bsums,  g_bsums);
    cudaGetSymbolAddress((void**)&edges,  g_edges);

    // --- embedding convert (independent of build; overlaps in-queue) ---
    size_t u4 = (size_t)n_users * (DIM / 4);
    size_t n4 = (size_t)n_total * (DIM / 4);
    convert_emb_kernel<<<(int)((n4 + 255) / 256), 256>>>(user_emb, item_emb, E, u4, n4);

    // --- unified CSR build ---
    cudaMemsetAsync(counts, 0, (size_t)L * sizeof(int));
    hist_all_kernel<<<(total_nnz + 255) / 256, 256>>>(a, counts, total_nnz);
    int nb = (L + SCAN_T - 1) / SCAN_T;
    scan1_kernel<<<nb, SCAN_T>>>(counts, offs, bsums, L);
    scan2_kernel<<<1, SCAN_T>>>(bsums, nb);
    scan3_kernel<<<nb, SCAN_T>>>(offs, bsums, L);
    cudaMemcpyAsync(cur, offs, (size_t)L * sizeof(int), cudaMemcpyDeviceToDevice);
    scatter_all_kernel<<<(total_nnz + 255) / 256, 256>>>(a, cur, edges, total_nnz);

    // per-matrix CSR offset pointers (global edge indices)
    const int* O[6];
    for (int k = 0; k < 6; k++) O[k] = offs + a.cbase[k];

    // --- fused propagation: per layer, stage order m2, m1, mcat ---
    // user matrix ids {u2=1, u1=0, ucat=2}; item = +3
    launch_spmm<true >(O[1], O[4], edges, E, T,  n_users, n_total);
    launch_spmm<true >(O[0], O[3], edges, T, S,  n_users, n_total);
    launch_spmm<true >(O[2], O[5], edges, S, H1, n_users, n_total);

    launch_spmm<true >(O[1], O[4], edges, H1, T, n_users, n_total);
    launch_spmm<true >(O[0], O[3], edges, T,  S, n_users, n_total);
    launch_spmm<true >(O[2], O[5], edges, S, H2, n_users, n_total);

    launch_spmm<true >(O[1], O[4], edges, H2, T, n_users, n_total);
    launch_spmm<true >(O[0], O[3], edges, T,  S, n_users, n_total);
    launch_spmm<false>(O[2], O[5], edges, S, H3, n_users, n_total);

    mean4_kernel<<<(int)((n4 + 255) / 256), 256>>>((float*)d_out, user_emb, item_emb,
                                                   H1, H2, H3, u4, n4);
}